// round 1
// baseline (speedup 1.0000x reference)
#include <cuda_runtime.h>

// Problem constants
#define MM   6
#define BB   128
#define TT   32
#define DINN 64
#define HHH  512
#define EEE  512
#define NEMB 32

// Fused per-(b,m) two-layer MLP with per-batch gathered weights.
// grid = B*M = 768 blocks, 256 threads.
// Thread owns 2 output columns (tid, tid+256) x all 32 rows.
__global__ __launch_bounds__(256, 2) void pmst_kernel(
    const float* __restrict__ state,   // [B, T, M*DIN]
    const int*   __restrict__ emb_ids, // [B]
    const float* __restrict__ W1,      // [M, NEMB, DIN, H]
    const float* __restrict__ b1,      // [M, NEMB, H]
    const float* __restrict__ W2,      // [M, NEMB, H, E]
    const float* __restrict__ b2,      // [M, NEMB, E]
    const float* __restrict__ te,      // [M, E]
    float* __restrict__ out)           // [B, M*T, E]
{
    extern __shared__ float smem[];
    float* Hs = smem;                // [T][H]   32*512 = 64KB
    float* Xs = smem + TT * HHH;     // [T][DIN] 32*64  =  8KB

    const int blk = blockIdx.x;      // b*M + m
    const int b   = blk / MM;
    const int m   = blk % MM;
    const int tid = threadIdx.x;
    const int e   = emb_ids[b];
    const long me = (long)m * NEMB + e;

    // ---- Load X tile (32 x 64) into shared, float4-vectorized ----
    {
        const float* xsrc = state + ((long)b * TT) * (MM * DINN) + m * DINN;
        // T*DIN/4 = 512 float4, 256 threads -> 2 each
        #pragma unroll
        for (int i = tid; i < TT * DINN / 4; i += 256) {
            int t = (i * 4) / DINN;
            int k = (i * 4) % DINN;
            float4 v = *(const float4*)(xsrc + (long)t * (MM * DINN) + k);
            *(float4*)(Xs + t * DINN + k) = v;
        }
    }
    __syncthreads();

    const int c0 = tid;
    const int c1 = tid + 256;

    // ---- Phase 1: H = relu(X @ W1 + b1), H kept in shared ----
    {
        const float* w1p = W1 + me * DINN * HHH;
        float acc0[TT], acc1[TT];
        #pragma unroll
        for (int t = 0; t < TT; t++) { acc0[t] = 0.f; acc1[t] = 0.f; }

        #pragma unroll 4
        for (int k = 0; k < DINN; k++) {
            float w0 = __ldg(w1p + (long)k * HHH + c0);
            float w1v = __ldg(w1p + (long)k * HHH + c1);
            #pragma unroll
            for (int t = 0; t < TT; t++) {
                float xv = Xs[t * DINN + k];   // warp-uniform -> LDS broadcast
                acc0[t] = fmaf(xv, w0,  acc0[t]);
                acc1[t] = fmaf(xv, w1v, acc1[t]);
            }
        }
        const float bb0 = b1[me * HHH + c0];
        const float bb1 = b1[me * HHH + c1];
        #pragma unroll
        for (int t = 0; t < TT; t++) {
            Hs[t * HHH + c0] = fmaxf(acc0[t] + bb0, 0.f);
            Hs[t * HHH + c1] = fmaxf(acc1[t] + bb1, 0.f);
        }
    }
    __syncthreads();

    // ---- Phase 2: Z = H @ W2 + b2 + type_embed ----
    {
        const float* w2p = W2 + me * HHH * EEE;
        float acc0[TT], acc1[TT];
        #pragma unroll
        for (int t = 0; t < TT; t++) { acc0[t] = 0.f; acc1[t] = 0.f; }

        #pragma unroll 2
        for (int k = 0; k < HHH; k++) {
            float w0 = __ldg(w2p + (long)k * EEE + c0);
            float w1v = __ldg(w2p + (long)k * EEE + c1);
            #pragma unroll
            for (int t = 0; t < TT; t++) {
                float hv = Hs[t * HHH + k];    // warp-uniform -> LDS broadcast
                acc0[t] = fmaf(hv, w0,  acc0[t]);
                acc1[t] = fmaf(hv, w1v, acc1[t]);
            }
        }

        const float add0 = b2[me * EEE + c0] + te[m * EEE + c0];
        const float add1 = b2[me * EEE + c1] + te[m * EEE + c1];
        // out[b, m*T + t, :]  -> (((b*M)+m)*T + t)*E
        float* op = out + (((long)b * MM + m) * TT) * EEE;
        #pragma unroll
        for (int t = 0; t < TT; t++) {
            op[(long)t * EEE + c0] = acc0[t] + add0;
            op[(long)t * EEE + c1] = acc1[t] + add1;
        }
    }
}

extern "C" void kernel_launch(void* const* d_in, const int* in_sizes, int n_in,
                              void* d_out, int out_size)
{
    const float* state   = (const float*)d_in[0];  // (B, T, M*DIN)
    const int*   emb_ids = (const int*)  d_in[1];  // (B,)
    const float* W1      = (const float*)d_in[2];  // (M, NEMB, DIN, H)
    const float* b1      = (const float*)d_in[3];  // (M, NEMB, H)
    const float* W2      = (const float*)d_in[4];  // (M, NEMB, H, E)
    const float* b2      = (const float*)d_in[5];  // (M, NEMB, E)
    const float* te      = (const float*)d_in[6];  // (M, E)
    float*       out     = (float*)d_out;          // (B, M*T, E)

    const int smem_bytes = (TT * HHH + TT * DINN) * (int)sizeof(float); // 73728
    cudaFuncSetAttribute(pmst_kernel,
                         cudaFuncAttributeMaxDynamicSharedMemorySize, smem_bytes);

    pmst_kernel<<<BB * MM, 256, smem_bytes>>>(state, emb_ids, W1, b1, W2, b2, te, out);
}

// round 2
// speedup vs baseline: 1.0906x; 1.0906x over previous
#include <cuda_runtime.h>

// Problem constants
#define MM   6
#define BB   128
#define TT   32
#define DINN 64
#define HHH  512
#define EEE  512
#define NEMB 32

#define TP        16   // t-pairs: pair (t, t+16)
#define XS_STRIDE 17   // row stride in float2 units (pad to dodge bank conflicts)
#define HS_STRIDE 17

typedef unsigned long long u64t;

__device__ __forceinline__ u64t pack2(float lo, float hi) {
    u64t r; asm("mov.b64 %0, {%1, %2};" : "=l"(r) : "f"(lo), "f"(hi)); return r;
}
__device__ __forceinline__ float2 unpack2(u64t v) {
    float2 r; asm("mov.b64 {%0, %1}, %2;" : "=f"(r.x), "=f"(r.y) : "l"(v)); return r;
}
// d = a*b + d (packed f32x2) — Blackwell-only, 2 FMAs per issue slot
__device__ __forceinline__ void fma2(u64t &d, u64t a, u64t b) {
    asm("fma.rn.f32x2 %0, %1, %2, %0;" : "+l"(d) : "l"(a), "l"(b));
}

// Fused per-(b,m) two-layer MLP with per-batch gathered weights.
// grid = B*M = 768 blocks, 256 threads; thread owns 2 output columns x 16 t-pairs.
// Activations live in shared transposed+packed: row k holds 16 float2 = (x[t][k], x[t+16][k]).
__global__ __launch_bounds__(256, 2) void pmst_kernel(
    const float* __restrict__ state,   // [B, T, M*DIN]
    const int*   __restrict__ emb_ids, // [B]
    const float* __restrict__ W1,      // [M, NEMB, DIN, H]
    const float* __restrict__ b1,      // [M, NEMB, H]
    const float* __restrict__ W2,      // [M, NEMB, H, E]
    const float* __restrict__ b2,      // [M, NEMB, E]
    const float* __restrict__ te,      // [M, E]
    float* __restrict__ out)           // [B, M*T, E]
{
    extern __shared__ u64t smem[];
    u64t* Xs = smem;                       // [DINN][XS_STRIDE] packed pairs
    u64t* Hs = smem + DINN * XS_STRIDE;    // [HHH][HS_STRIDE]  packed pairs

    const int blk = blockIdx.x;            // b*M + m
    const int b   = blk / MM;
    const int m   = blk % MM;
    const int tid = threadIdx.x;
    const int e   = emb_ids[b];
    const long me = (long)m * NEMB + e;

    const int c0 = tid;
    const int c1 = tid + 256;

    // ---- Load X tile, transposing into packed-pair layout ----
    // Xs[k][tp] = (x[tp][k], x[tp+16][k])
    {
        const float* xsrc = state + ((long)b * TT) * (MM * DINN) + m * DINN;
        #pragma unroll
        for (int idx = tid; idx < TP * DINN; idx += 256) {
            int tp = idx >> 6;          // 0..15
            int k  = idx & (DINN - 1);  // 0..63  (consecutive tid -> consecutive k: coalesced)
            float v0 = __ldg(xsrc + (long)tp        * (MM * DINN) + k);
            float v1 = __ldg(xsrc + (long)(tp + TP) * (MM * DINN) + k);
            Xs[k * XS_STRIDE + tp] = pack2(v0, v1);
        }
    }
    __syncthreads();

    // ---- Phase 1: H = relu(X @ W1 + b1) -> packed pairs in Hs ----
    {
        const float* w1p = W1 + me * (long)DINN * HHH;
        u64t accA[TP], accB[TP];
        #pragma unroll
        for (int tp = 0; tp < TP; tp++) { accA[tp] = 0ull; accB[tp] = 0ull; }

        #pragma unroll 2
        for (int k = 0; k < DINN; k++) {
            float w0  = __ldg(w1p + (long)k * HHH + c0);
            float w1v = __ldg(w1p + (long)k * HHH + c1);
            u64t wA = pack2(w0,  w0);
            u64t wB = pack2(w1v, w1v);
            const u64t* xrow = Xs + k * XS_STRIDE;
            #pragma unroll
            for (int tp = 0; tp < TP; tp++) {
                u64t a = xrow[tp];          // LDS.64, warp-uniform broadcast
                fma2(accA[tp], a, wA);
                fma2(accB[tp], a, wB);
            }
        }

        const float bb0 = b1[me * HHH + c0];
        const float bb1 = b1[me * HHH + c1];
        #pragma unroll
        for (int tp = 0; tp < TP; tp++) {
            float2 vA = unpack2(accA[tp]);
            float2 vB = unpack2(accB[tp]);
            vA.x = fmaxf(vA.x + bb0, 0.f); vA.y = fmaxf(vA.y + bb0, 0.f);
            vB.x = fmaxf(vB.x + bb1, 0.f); vB.y = fmaxf(vB.y + bb1, 0.f);
            Hs[c0 * HS_STRIDE + tp] = pack2(vA.x, vA.y);
            Hs[c1 * HS_STRIDE + tp] = pack2(vB.x, vB.y);
        }
    }
    __syncthreads();

    // ---- Phase 2: Z = H @ W2 + b2 + type_embed ----
    {
        const float* w2p = W2 + me * (long)HHH * EEE;
        u64t accA[TP], accB[TP];
        #pragma unroll
        for (int tp = 0; tp < TP; tp++) { accA[tp] = 0ull; accB[tp] = 0ull; }

        #pragma unroll 2
        for (int k = 0; k < HHH; k++) {
            float w0  = __ldg(w2p + (long)k * EEE + c0);
            float w1v = __ldg(w2p + (long)k * EEE + c1);
            u64t wA = pack2(w0,  w0);
            u64t wB = pack2(w1v, w1v);
            const u64t* hrow = Hs + k * HS_STRIDE;
            #pragma unroll
            for (int tp = 0; tp < TP; tp++) {
                u64t a = hrow[tp];          // LDS.64, warp-uniform broadcast
                fma2(accA[tp], a, wA);
                fma2(accB[tp], a, wB);
            }
        }

        const float add0 = b2[me * EEE + c0] + te[m * EEE + c0];
        const float add1 = b2[me * EEE + c1] + te[m * EEE + c1];
        // out[b, m*T + t, :]  -> (((b*M)+m)*T + t)*E
        float* op = out + (((long)b * MM + m) * TT) * EEE;
        #pragma unroll
        for (int tp = 0; tp < TP; tp++) {
            float2 vA = unpack2(accA[tp]);
            float2 vB = unpack2(accB[tp]);
            op[(long)tp        * EEE + c0] = vA.x + add0;
            op[(long)(tp + TP) * EEE + c0] = vA.y + add0;
            op[(long)tp        * EEE + c1] = vB.x + add1;
            op[(long)(tp + TP) * EEE + c1] = vB.y + add1;
        }
    }
}

extern "C" void kernel_launch(void* const* d_in, const int* in_sizes, int n_in,
                              void* d_out, int out_size)
{
    const float* state   = (const float*)d_in[0];  // (B, T, M*DIN)
    const int*   emb_ids = (const int*)  d_in[1];  // (B,)
    const float* W1      = (const float*)d_in[2];  // (M, NEMB, DIN, H)
    const float* b1      = (const float*)d_in[3];  // (M, NEMB, H)
    const float* W2      = (const float*)d_in[4];  // (M, NEMB, H, E)
    const float* b2      = (const float*)d_in[5];  // (M, NEMB, E)
    const float* te      = (const float*)d_in[6];  // (M, E)
    float*       out     = (float*)d_out;          // (B, M*T, E)

    const int smem_bytes = (DINN * XS_STRIDE + HHH * HS_STRIDE) * (int)sizeof(u64t); // 78336
    cudaFuncSetAttribute(pmst_kernel,
                         cudaFuncAttributeMaxDynamicSharedMemorySize, smem_bytes);

    pmst_kernel<<<BB * MM, 256, smem_bytes>>>(state, emb_ids, W1, b1, W2, b2, te, out);
}

// round 4
// speedup vs baseline: 3.2173x; 2.9500x over previous
#include <cuda_runtime.h>
#include <cstdint>

#define MM   6
#define BB   128
#define TT   32
#define DINN 64
#define HHH  512
#define EEE  512
#define NEMB 32

#define XS_STRIDE 68    // floats; 68 mod 32 = 4 -> conflict-free A-fragment LDS
#define HS_STRIDE 516   // floats; 516 mod 32 = 4

// f32 -> tf32 bits, round-to-nearest (keeps accuracy vs truncation)
__device__ __forceinline__ uint32_t f2tf(float f) {
    uint32_t r; asm("cvt.rna.tf32.f32 %0, %1;" : "=r"(r) : "f"(f)); return r;
}

// D += A(16x8,row) * B(8x8,col)  tf32 inputs, f32 accum
__device__ __forceinline__ void mma8(float* d, const uint32_t* a, const uint32_t* b) {
    asm volatile(
        "mma.sync.aligned.m16n8k8.row.col.f32.tf32.tf32.f32 "
        "{%0,%1,%2,%3}, {%4,%5,%6,%7}, {%8,%9}, {%0,%1,%2,%3};"
        : "+f"(d[0]), "+f"(d[1]), "+f"(d[2]), "+f"(d[3])
        : "r"(a[0]), "r"(a[1]), "r"(a[2]), "r"(a[3]), "r"(b[0]), "r"(b[1]));
}

// Fused per-(b,m) two-layer MLP. grid = B*M, 256 threads (8 warps).
// Warp w owns output columns [w*64, w*64+64). mma tiles: 2 x (m16) x 8 x (n8).
__global__ __launch_bounds__(256, 2) void pmst_mma_kernel(
    const float* __restrict__ state,   // [B, T, M*DIN]
    const int*   __restrict__ emb_ids, // [B]
    const float* __restrict__ W1,      // [M, NEMB, DIN, H]
    const float* __restrict__ b1,      // [M, NEMB, H]
    const float* __restrict__ W2,      // [M, NEMB, H, E]
    const float* __restrict__ b2,      // [M, NEMB, E]
    const float* __restrict__ te,      // [M, E]
    float* __restrict__ out)           // [B, M*T, E]
{
    extern __shared__ uint32_t sm[];
    uint32_t* Xs = sm;                     // [32][XS_STRIDE] tf32 bits
    uint32_t* Hs = sm + TT * XS_STRIDE;    // [32][HS_STRIDE] tf32 bits

    const int tid  = threadIdx.x;
    const int wid  = tid >> 5;
    const int lane = tid & 31;
    const int g    = lane >> 2;   // groupID      (0..7)
    const int tg   = lane & 3;    // thread-in-grp (0..3)

    const int b = blockIdx.x / MM;
    const int m = blockIdx.x % MM;
    const int e = __ldg(emb_ids + b);
    const long me = (long)m * NEMB + e;

    const float* W1p = W1 + me * (DINN * HHH);
    const float* W2p = W2 + me * ((long)HHH * EEE);
    const float* b1p = b1 + me * HHH;
    const float* b2p = b2 + me * EEE;
    const float* tep = te + (long)m * EEE;

    // ---- Stage X (32x64) into smem as tf32 bits ----
    {
        const float* xs = state + (long)b * TT * (MM * DINN) + m * DINN;
        #pragma unroll
        for (int i = tid; i < TT * DINN; i += 256) {
            int t = i >> 6, k = i & 63;
            Xs[t * XS_STRIDE + k] = f2tf(__ldg(xs + (long)t * (MM * DINN) + k));
        }
    }
    __syncthreads();

    const int ncol0 = wid * 64;
    float acc[2][8][4];

    // ================= GEMM1: H = relu(X @ W1 + b1) =================
    #pragma unroll
    for (int mt = 0; mt < 2; mt++)
        #pragma unroll
        for (int nt = 0; nt < 8; nt++)
            #pragma unroll
            for (int i = 0; i < 4; i++) acc[mt][nt][i] = 0.f;

    {
        const uint32_t* xb = Xs + g * XS_STRIDE + tg;
        const float*    wb = W1p + (long)tg * HHH + ncol0 + g;
        #pragma unroll
        for (int kc = 0; kc < 8; kc++) {
            const int k0 = kc * 8;
            uint32_t a[2][4];
            #pragma unroll
            for (int mt = 0; mt < 2; mt++) {
                const uint32_t* xp = xb + mt * 16 * XS_STRIDE + k0;
                a[mt][0] = xp[0];
                a[mt][1] = xp[8 * XS_STRIDE];
                a[mt][2] = xp[4];
                a[mt][3] = xp[8 * XS_STRIDE + 4];
            }
            const float* wp = wb + (long)k0 * HHH;
            #pragma unroll
            for (int nt = 0; nt < 8; nt++) {
                uint32_t bf[2];
                bf[0] = f2tf(__ldg(wp + nt * 8));             // (k0+tg,   n)
                bf[1] = f2tf(__ldg(wp + 4 * HHH + nt * 8));   // (k0+tg+4, n)
                mma8(acc[0][nt], a[0], bf);
                mma8(acc[1][nt], a[1], bf);
            }
        }
    }

    // ---- Epilogue1: relu + bias -> Hs (tf32 bits) ----
    #pragma unroll
    for (int nt = 0; nt < 8; nt++) {
        const int n = ncol0 + nt * 8 + tg * 2;
        const float bb0 = __ldg(b1p + n);
        const float bb1 = __ldg(b1p + n + 1);
        #pragma unroll
        for (int mt = 0; mt < 2; mt++) {
            const int r0 = mt * 16 + g;
            Hs[r0 * HS_STRIDE + n]           = f2tf(fmaxf(acc[mt][nt][0] + bb0, 0.f));
            Hs[r0 * HS_STRIDE + n + 1]       = f2tf(fmaxf(acc[mt][nt][1] + bb1, 0.f));
            Hs[(r0 + 8) * HS_STRIDE + n]     = f2tf(fmaxf(acc[mt][nt][2] + bb0, 0.f));
            Hs[(r0 + 8) * HS_STRIDE + n + 1] = f2tf(fmaxf(acc[mt][nt][3] + bb1, 0.f));
        }
    }
    __syncthreads();

    // ================= GEMM2: Z = H @ W2 + b2 + te =================
    #pragma unroll
    for (int mt = 0; mt < 2; mt++)
        #pragma unroll
        for (int nt = 0; nt < 8; nt++)
            #pragma unroll
            for (int i = 0; i < 4; i++) acc[mt][nt][i] = 0.f;

    {
        const uint32_t* hb = Hs + g * HS_STRIDE + tg;
        const float*    wb = W2p + (long)tg * EEE + ncol0 + g;
        #pragma unroll 4
        for (int kc = 0; kc < 64; kc++) {
            const int k0 = kc * 8;
            uint32_t a[2][4];
            #pragma unroll
            for (int mt = 0; mt < 2; mt++) {
                const uint32_t* hp = hb + mt * 16 * HS_STRIDE + k0;
                a[mt][0] = hp[0];
                a[mt][1] = hp[8 * HS_STRIDE];
                a[mt][2] = hp[4];
                a[mt][3] = hp[8 * HS_STRIDE + 4];
            }
            const float* wp = wb + (long)k0 * EEE;
            #pragma unroll
            for (int nt = 0; nt < 8; nt++) {
                uint32_t bf[2];
                bf[0] = f2tf(__ldg(wp + nt * 8));
                bf[1] = f2tf(__ldg(wp + 4 * EEE + nt * 8));
                mma8(acc[0][nt], a[0], bf);
                mma8(acc[1][nt], a[1], bf);
            }
        }
    }

    // ---- Epilogue2: out[b, m*T + t, o] ----
    {
        float* op = out + ((long)b * MM + m) * TT * EEE;
        #pragma unroll
        for (int nt = 0; nt < 8; nt++) {
            const int n = ncol0 + nt * 8 + tg * 2;
            const float a0 = __ldg(b2p + n)     + __ldg(tep + n);
            const float a1 = __ldg(b2p + n + 1) + __ldg(tep + n + 1);
            #pragma unroll
            for (int mt = 0; mt < 2; mt++) {
                const int r0 = mt * 16 + g;
                float2 v0 = make_float2(acc[mt][nt][0] + a0, acc[mt][nt][1] + a1);
                float2 v1 = make_float2(acc[mt][nt][2] + a0, acc[mt][nt][3] + a1);
                *(float2*)(op + (long)r0       * EEE + n) = v0;
                *(float2*)(op + (long)(r0 + 8) * EEE + n) = v1;
            }
        }
    }
}

extern "C" void kernel_launch(void* const* d_in, const int* in_sizes, int n_in,
                              void* d_out, int out_size)
{
    const float* state   = (const float*)d_in[0];
    const int*   emb_ids = (const int*)  d_in[1];
    const float* W1      = (const float*)d_in[2];
    const float* b1      = (const float*)d_in[3];
    const float* W2      = (const float*)d_in[4];
    const float* b2      = (const float*)d_in[5];
    const float* te      = (const float*)d_in[6];
    float*       out     = (float*)d_out;

    const int smem_bytes = (TT * XS_STRIDE + TT * HS_STRIDE) * (int)sizeof(uint32_t); // 74752
    cudaFuncSetAttribute(pmst_mma_kernel,
                         cudaFuncAttributeMaxDynamicSharedMemorySize, smem_bytes);

    pmst_mma_kernel<<<BB * MM, 256, smem_bytes>>>(state, emb_ids, W1, b1, W2, b2, te, out);
}

// round 5
// speedup vs baseline: 3.9155x; 1.2170x over previous
#include <cuda_runtime.h>
#include <cstdint>

#define MM   6
#define BB   128
#define TT   32
#define DINN 64
#define HHH  512
#define EEE  512
#define NEMB 32

#define MAXC      80     // max chunks: (128 + 32)/2
#define ROWS      64     // token rows per block: 2 batches x 32
#define XS_STRIDE 68     // floats; mod 32 = 4 -> conflict-free fragment LDS
#define HS_STRIDE 516    // floats; mod 32 = 4

// chunk table: (b0, b1) pairs sharing one emb id, grouped by emb
__device__ int g_chunk_b0[MAXC];
__device__ int g_chunk_b1[MAXC];
__device__ int g_chunk_e [MAXC];
__device__ int g_nchunks;

__global__ void pmst_prepass(const int* __restrict__ emb_ids) {
    const int e = threadIdx.x;             // 0..31, one thread per emb value
    int cnt = 0;
    for (int b = 0; b < BB; b++) cnt += (emb_ids[b] == e);
    int pairs = (cnt + 1) >> 1;
    // inclusive warp prefix sum
    int off = pairs;
    #pragma unroll
    for (int d = 1; d < 32; d <<= 1) {
        int v = __shfl_up_sync(0xFFFFFFFFu, off, d);
        if (e >= d) off += v;
    }
    if (e == 31) g_nchunks = off;
    int idx = off - pairs;
    int prev = -1;
    for (int b = 0; b < BB; b++) {
        if (emb_ids[b] == e) {
            if (prev < 0) prev = b;
            else {
                g_chunk_b0[idx] = prev; g_chunk_b1[idx] = b; g_chunk_e[idx] = e;
                idx++; prev = -1;
            }
        }
    }
    if (prev >= 0) { g_chunk_b0[idx] = prev; g_chunk_b1[idx] = prev; g_chunk_e[idx] = e; }
}

// f32 -> tf32 bits, round-to-nearest
__device__ __forceinline__ uint32_t f2tf(float f) {
    uint32_t r; asm("cvt.rna.tf32.f32 %0, %1;" : "=r"(r) : "f"(f)); return r;
}

__device__ __forceinline__ void mma8(float* d, const uint32_t* a, const uint32_t* b) {
    asm volatile(
        "mma.sync.aligned.m16n8k8.row.col.f32.tf32.tf32.f32 "
        "{%0,%1,%2,%3}, {%4,%5,%6,%7}, {%8,%9}, {%0,%1,%2,%3};"
        : "+f"(d[0]), "+f"(d[1]), "+f"(d[2]), "+f"(d[3])
        : "r"(a[0]), "r"(a[1]), "r"(a[2]), "r"(a[3]), "r"(b[0]), "r"(b[1]));
}

// grid = (MAXC, MM); block = 512 threads (16 warps).
// Block (c, m): 2 batches sharing emb e -> 64 token rows; warp owns 32 output cols.
__global__ __launch_bounds__(512, 1) void pmst_mma_kernel(
    const float* __restrict__ state,   // [B, T, M*DIN]
    const float* __restrict__ W1,      // [M, NEMB, DIN, H]
    const float* __restrict__ b1,      // [M, NEMB, H]
    const float* __restrict__ W2,      // [M, NEMB, H, E]
    const float* __restrict__ b2,      // [M, NEMB, E]
    const float* __restrict__ te,      // [M, E]
    float* __restrict__ out)           // [B, M*T, E]
{
    const int c = blockIdx.x;
    if (c >= g_nchunks) return;
    const int m  = blockIdx.y;
    const int e  = g_chunk_e[c];
    const int b0 = g_chunk_b0[c];
    const int b1v = g_chunk_b1[c];

    extern __shared__ uint32_t smu[];
    uint32_t* Xs = smu;                        // [ROWS][XS_STRIDE]
    uint32_t* Hs = smu + ROWS * XS_STRIDE;     // [ROWS][HS_STRIDE]

    const int tid  = threadIdx.x;
    const int wid  = tid >> 5;
    const int lane = tid & 31;
    const int g    = lane >> 2;    // 0..7
    const int tg   = lane & 3;     // 0..3

    const long me = (long)m * NEMB + e;
    const float* W1p = W1 + me * (DINN * HHH);
    const float* W2p = W2 + me * ((long)HHH * EEE);
    const float* b1p = b1 + me * HHH;
    const float* b2p = b2 + me * EEE;
    const float* tep = te + (long)m * EEE;

    // ---- Stage X: 64 rows (2 batches x 32 tokens) ----
    {
        #pragma unroll
        for (int i = tid; i < ROWS * DINN; i += 512) {
            int tr = i >> 6, k = i & 63;
            int bb = (tr < TT) ? b0 : b1v;
            int t  = tr & (TT - 1);
            Xs[tr * XS_STRIDE + k] =
                f2tf(__ldg(state + ((long)bb * TT + t) * (MM * DINN) + m * DINN + k));
        }
    }
    __syncthreads();

    const int ncol0 = wid * 32;
    float acc[4][4][4];   // [m-tile 16rows][n-tile 8cols][frag]

    // ================= GEMM1: H = relu(X @ W1 + b1) =================
    #pragma unroll
    for (int mt = 0; mt < 4; mt++)
        #pragma unroll
        for (int nt = 0; nt < 4; nt++)
            #pragma unroll
            for (int i = 0; i < 4; i++) acc[mt][nt][i] = 0.f;
    {
        const uint32_t* xb = Xs + g * XS_STRIDE + tg;
        const float*    wb = W1p + (long)tg * HHH + ncol0 + g;
        #pragma unroll
        for (int kc = 0; kc < 8; kc++) {
            const int k0 = kc * 8;
            uint32_t a[4][4];
            #pragma unroll
            for (int mt = 0; mt < 4; mt++) {
                const uint32_t* xp = xb + mt * 16 * XS_STRIDE + k0;
                a[mt][0] = xp[0];
                a[mt][1] = xp[8 * XS_STRIDE];
                a[mt][2] = xp[4];
                a[mt][3] = xp[8 * XS_STRIDE + 4];
            }
            const float* wp = wb + (long)k0 * HHH;
            #pragma unroll
            for (int nt = 0; nt < 4; nt++) {
                uint32_t bf[2];
                bf[0] = f2tf(__ldg(wp + nt * 8));
                bf[1] = f2tf(__ldg(wp + 4 * HHH + nt * 8));
                #pragma unroll
                for (int mt = 0; mt < 4; mt++) mma8(acc[mt][nt], a[mt], bf);
            }
        }
    }

    // ---- Epilogue1: relu + bias -> Hs ----
    #pragma unroll
    for (int nt = 0; nt < 4; nt++) {
        const int n = ncol0 + nt * 8 + tg * 2;
        const float bb0 = __ldg(b1p + n);
        const float bb1 = __ldg(b1p + n + 1);
        #pragma unroll
        for (int mt = 0; mt < 4; mt++) {
            const int r0 = mt * 16 + g;
            Hs[r0 * HS_STRIDE + n]           = f2tf(fmaxf(acc[mt][nt][0] + bb0, 0.f));
            Hs[r0 * HS_STRIDE + n + 1]       = f2tf(fmaxf(acc[mt][nt][1] + bb1, 0.f));
            Hs[(r0 + 8) * HS_STRIDE + n]     = f2tf(fmaxf(acc[mt][nt][2] + bb0, 0.f));
            Hs[(r0 + 8) * HS_STRIDE + n + 1] = f2tf(fmaxf(acc[mt][nt][3] + bb1, 0.f));
        }
    }
    __syncthreads();

    // ================= GEMM2: Z = H @ W2 + b2 + te =================
    #pragma unroll
    for (int mt = 0; mt < 4; mt++)
        #pragma unroll
        for (int nt = 0; nt < 4; nt++)
            #pragma unroll
            for (int i = 0; i < 4; i++) acc[mt][nt][i] = 0.f;
    {
        const uint32_t* hb = Hs + g * HS_STRIDE + tg;
        const float*    wb = W2p + (long)tg * EEE + ncol0 + g;
        #pragma unroll 4
        for (int kc = 0; kc < 64; kc++) {
            const int k0 = kc * 8;
            uint32_t a[4][4];
            #pragma unroll
            for (int mt = 0; mt < 4; mt++) {
                const uint32_t* hp = hb + mt * 16 * HS_STRIDE + k0;
                a[mt][0] = hp[0];
                a[mt][1] = hp[8 * HS_STRIDE];
                a[mt][2] = hp[4];
                a[mt][3] = hp[8 * HS_STRIDE + 4];
            }
            const float* wp = wb + (long)k0 * EEE;
            #pragma unroll
            for (int nt = 0; nt < 4; nt++) {
                uint32_t bf[2];
                bf[0] = f2tf(__ldg(wp + nt * 8));
                bf[1] = f2tf(__ldg(wp + 4 * EEE + nt * 8));
                #pragma unroll
                for (int mt = 0; mt < 4; mt++) mma8(acc[mt][nt], a[mt], bf);
            }
        }
    }

    // ---- Epilogue2: out[b, m*T + t, o] ----
    {
        float* op0 = out + ((long)b0  * MM + m) * TT * EEE;
        float* op1 = out + ((long)b1v * MM + m) * TT * EEE;
        #pragma unroll
        for (int nt = 0; nt < 4; nt++) {
            const int n = ncol0 + nt * 8 + tg * 2;
            const float a0 = __ldg(b2p + n)     + __ldg(tep + n);
            const float a1 = __ldg(b2p + n + 1) + __ldg(tep + n + 1);
            #pragma unroll
            for (int mt = 0; mt < 4; mt++) {
                const int r0 = mt * 16 + g;        // token row in [0,64)
                const int r1 = r0 + 8;
                float* p0 = ((r0 < TT) ? op0 : op1) + (long)(r0 & (TT - 1)) * EEE + n;
                float* p1 = ((r1 < TT) ? op0 : op1) + (long)(r1 & (TT - 1)) * EEE + n;
                *(float2*)p0 = make_float2(acc[mt][nt][0] + a0, acc[mt][nt][1] + a1);
                *(float2*)p1 = make_float2(acc[mt][nt][2] + a0, acc[mt][nt][3] + a1);
            }
        }
    }
}

extern "C" void kernel_launch(void* const* d_in, const int* in_sizes, int n_in,
                              void* d_out, int out_size)
{
    const float* state   = (const float*)d_in[0];
    const int*   emb_ids = (const int*)  d_in[1];
    const float* W1      = (const float*)d_in[2];
    const float* b1      = (const float*)d_in[3];
    const float* W2      = (const float*)d_in[4];
    const float* b2      = (const float*)d_in[5];
    const float* te      = (const float*)d_in[6];
    float*       out     = (float*)d_out;

    pmst_prepass<<<1, 32>>>(emb_ids);

    const int smem_bytes = (ROWS * XS_STRIDE + ROWS * HS_STRIDE) * (int)sizeof(uint32_t); // 149504
    cudaFuncSetAttribute(pmst_mma_kernel,
                         cudaFuncAttributeMaxDynamicSharedMemorySize, smem_bytes);

    dim3 grid(MAXC, MM);
    pmst_mma_kernel<<<grid, 512, smem_bytes>>>(state, W1, b1, W2, b2, te, out);
}